// round 6
// baseline (speedup 1.0000x reference)
#include <cuda_runtime.h>
#include <cuda_bf16.h>

// Problem constants
#define B_  16
#define T_  512
#define H_  2048
#define W_STRIDE 4096   // W is [H, 2H] row-major
#define NCTA 128
#define NTHR 256

// 64 MB scratch for u = x @ Wx^T + b   (B*T, H)
__device__ float g_u[B_ * T_ * H_];
// grid barrier counter (monotonic within one launch; reset per replay)
__device__ unsigned g_arrive;

__global__ void init_kernel() { g_arrive = 0u; }

// packed f32x2 FMA: d = a*b + c
__device__ __forceinline__ unsigned long long ffma2(
    unsigned long long a, unsigned long long b, unsigned long long c)
{
    unsigned long long d;
    asm("fma.rn.f32x2 %0, %1, %2, %3;" : "=l"(d) : "l"(a), "l"(b), "l"(c));
    return d;
}
__device__ __forceinline__ unsigned long long pack2(float x)
{
    unsigned long long r;
    asm("mov.b64 %0, {%1, %1};" : "=l"(r) : "f"(x));
    return r;
}
// grid-barrier primitives: no CCTL.IVALL (keep L1 resident)
__device__ __forceinline__ void red_release_add(unsigned* p, unsigned v)
{
    asm volatile("red.release.gpu.global.add.u32 [%0], %1;" :: "l"(p), "r"(v) : "memory");
}
__device__ __forceinline__ unsigned ld_acquire(unsigned* p)
{
    unsigned v;
    asm volatile("ld.acquire.gpu.global.u32 %0, [%1];" : "=r"(v) : "l"(p) : "memory");
    return v;
}
// cp.async 16B, L2-only (.cg) — does not pollute L1
__device__ __forceinline__ void cp_async16(unsigned smem_addr, const void* gptr)
{
    asm volatile("cp.async.cg.shared.global [%0], [%1], 16;"
                 :: "r"(smem_addr), "l"(gptr));
}
__device__ __forceinline__ void cp_commit()
{
    asm volatile("cp.async.commit_group;");
}
template<int N> __device__ __forceinline__ void cp_wait()
{
    asm volatile("cp.async.wait_group %0;" :: "n"(N));
}

// ---------------------------------------------------------------------------
// Phase 1: u[m, n] = sum_k X[m,k] * W[n, k] + bias[n]
// 128x128 tile, TK=8, 256 threads, 8x8 microtile, f32x2 packed FMA.
// ---------------------------------------------------------------------------
#define P1_TM 128
#define P1_TN 128
#define P1_TK 8

__global__ __launch_bounds__(256) void u_gemm_kernel(
    const float* __restrict__ X, const float* __restrict__ W,
    const float* __restrict__ bias, float* __restrict__ U)
{
    __shared__ __align__(16) float As[P1_TK][P1_TM + 4];
    __shared__ __align__(16) float Bs[P1_TK][P1_TN + 4];

    const int n0 = blockIdx.x * P1_TN;
    const int m0 = blockIdx.y * P1_TM;
    const int tid = threadIdx.x;
    const int tx = tid & 15;
    const int ty = tid >> 4;
    const int lrow = tid >> 1;
    const int lk4  = (tid & 1) * 4;

    unsigned long long acc[8][4];
#pragma unroll
    for (int i = 0; i < 8; i++)
#pragma unroll
        for (int j = 0; j < 4; j++) acc[i][j] = 0ull;

    const float* xrow = X + (size_t)(m0 + lrow) * H_ + lk4;
    const float* wrow = W + (size_t)(n0 + lrow) * W_STRIDE + lk4;

    for (int k0 = 0; k0 < H_; k0 += P1_TK) {
        float4 xa = __ldg((const float4*)(xrow + k0));
        float4 wb = __ldg((const float4*)(wrow + k0));
        As[lk4 + 0][lrow] = xa.x; As[lk4 + 1][lrow] = xa.y;
        As[lk4 + 2][lrow] = xa.z; As[lk4 + 3][lrow] = xa.w;
        Bs[lk4 + 0][lrow] = wb.x; Bs[lk4 + 1][lrow] = wb.y;
        Bs[lk4 + 2][lrow] = wb.z; Bs[lk4 + 3][lrow] = wb.w;
        __syncthreads();

#pragma unroll
        for (int kk = 0; kk < P1_TK; kk++) {
            float4 a0 = *(const float4*)&As[kk][ty * 8];
            float4 a1 = *(const float4*)&As[kk][ty * 8 + 4];
            unsigned long long bp[4];
#pragma unroll
            for (int j = 0; j < 4; j++)
                bp[j] = *(const unsigned long long*)&Bs[kk][tx * 8 + j * 2];

            unsigned long long ap[8];
            ap[0] = pack2(a0.x); ap[1] = pack2(a0.y); ap[2] = pack2(a0.z); ap[3] = pack2(a0.w);
            ap[4] = pack2(a1.x); ap[5] = pack2(a1.y); ap[6] = pack2(a1.z); ap[7] = pack2(a1.w);
#pragma unroll
            for (int i = 0; i < 8; i++)
#pragma unroll
                for (int j = 0; j < 4; j++)
                    acc[i][j] = ffma2(ap[i], bp[j], acc[i][j]);
        }
        __syncthreads();
    }

#pragma unroll
    for (int i = 0; i < 8; i++) {
        size_t m = m0 + ty * 8 + i;
#pragma unroll
        for (int j = 0; j < 4; j++) {
            int n = n0 + tx * 8 + j * 2;
            float2 f = *(float2*)&acc[i][j];
            f.x += bias[n];
            f.y += bias[n + 1];
            *(float2*)&U[m * H_ + n] = f;
        }
    }
}

// ---------------------------------------------------------------------------
// Phase 2: persistent recurrence, cp.async chunked h-staging.
// 128 CTAs x 256 thr, 1 CTA/SM, fence-free spin barrier.
// CTA owns 16 g. Warp = gGroup(2x8g) x bGroup(2x8b) x kHalf(2x256k-per-chunk).
// h staged in 4 chunks of [16 b][512 k] (32 KB) through a 2-buffer pipeline.
// smem ~66 KB => L1 carveout ~161 KB => full 128 KB W slice stays L1-resident.
// ---------------------------------------------------------------------------
#define CHUNK_K   512
#define NCHUNK    (H_ / CHUNK_K)          // 4
#define BUF_FLTS  (B_ * CHUNK_K)          // 8192 floats = 32 KB
#define SMEM_FLOATS (2 * BUF_FLTS + 256 + 256)

__global__ __launch_bounds__(NTHR, 1) void rnn_persistent_kernel(
    const float* __restrict__ W, const float* __restrict__ U,
    float* __restrict__ out)
{
    extern __shared__ __align__(16) float hs[];   // [2][16][512]
    float* us  = hs + 2 * BUF_FLTS;               // [16 b][16 gl]
    float* red = us + 256;                        // [16 gl][16 b]

    const int tid  = threadIdx.x;
    const int warp = tid >> 5;
    const int lane = tid & 31;
    const int gGroup = warp & 1;
    const int bGroup = (warp >> 1) & 1;
    const int kHalf  = warp >> 2;
    const int gbase = blockIdx.x * 16;

    // W row bases (Wh part)
    const float* wrow[8];
#pragma unroll
    for (int g = 0; g < 8; g++)
        wrow[g] = W + (size_t)(gbase + gGroup * 8 + g) * W_STRIDE + H_;

    // smem u32 base addresses for cp.async
    const unsigned hs_s = (unsigned)__cvta_generic_to_shared(hs);

    // ---- t = 0: out[:, 0, slice] = U[:, 0, slice] ----
    {
        int b = tid >> 4;
        int gl = tid & 15;
        int o = (b * T_) * H_ + gbase + gl;
        out[o] = __ldcg(&U[o]);
    }
    __syncthreads();
    if (tid == 0) red_release_add(&g_arrive, 1u);

    for (int t = 1; t < T_; t++) {
        // ---- grid barrier (acquire; no L1 flush) ----
        if (tid == 0) {
            unsigned target = (unsigned)(NCTA * t);
            while (ld_acquire(&g_arrive) < target) __nanosleep(32);
        }
        __syncthreads();

        const float* hrow = out;   // h_{t-1} lives at out[:, t-1, :]
        const size_t hoff = (size_t)(t - 1) * H_;

        // stage this step's U slice (L2 load; small)
        {
            int b = tid >> 4;
            int gl = tid & 15;
            us[tid] = __ldcg(&U[((size_t)(b * T_ + t)) * H_ + gbase + gl]);
        }

        // ---- prologue: stage chunk 0 ----
        {
#pragma unroll
            for (int j = 0; j < 8; j++) {
                int idx = tid + j * NTHR;          // 0..2047
                int b   = idx >> 7;                // 0..15
                int k4  = idx & 127;               // float4 index in chunk
                cp_async16(hs_s + (unsigned)((b * CHUNK_K + k4 * 4) * 4),
                           hrow + ((size_t)b * T_) * H_ + hoff + k4 * 4);
            }
            cp_commit();
        }

        // ---- accumulators ----
        unsigned long long acc[8][8];
#pragma unroll
        for (int b = 0; b < 8; b++)
#pragma unroll
            for (int g = 0; g < 8; g++) acc[b][g] = 0ull;

        // ---- chunk pipeline ----
#pragma unroll
        for (int c = 0; c < NCHUNK; c++) {
            const int cur = c & 1;
            if (c < NCHUNK - 1) {       // issue stage of chunk c+1
                const int nxt = (c + 1) & 1;
                const int kc0 = (c + 1) * CHUNK_K;
#pragma unroll
                for (int j = 0; j < 8; j++) {
                    int idx = tid + j * NTHR;
                    int b   = idx >> 7;
                    int k4  = idx & 127;
                    cp_async16(hs_s + (unsigned)((nxt * BUF_FLTS + b * CHUNK_K + k4 * 4) * 4),
                               hrow + ((size_t)b * T_) * H_ + hoff + kc0 + k4 * 4);
                }
                cp_commit();
                cp_wait<1>();           // chunk c complete (c+1 still pending)
            } else {
                cp_wait<0>();           // last chunk complete
            }
            __syncthreads();

            const float* buf = hs + cur * BUF_FLTS;
            const int kbase = c * CHUNK_K + kHalf * 256;

#pragma unroll
            for (int it = 0; it < 2; it++) {
                const int k0 = it * 128 + lane * 4;
                ulonglong2 wv[8];
#pragma unroll
                for (int g = 0; g < 8; g++)
                    wv[g] = __ldg((const ulonglong2*)&wrow[g][kbase + k0]);
#pragma unroll
                for (int b = 0; b < 8; b++) {
                    ulonglong2 hv = *(const ulonglong2*)
                        &buf[(bGroup * 8 + b) * CHUNK_K + kHalf * 256 + k0];
#pragma unroll
                    for (int g = 0; g < 8; g++) {
                        acc[b][g] = ffma2(hv.x, wv[g].x, acc[b][g]);
                        acc[b][g] = ffma2(hv.y, wv[g].y, acc[b][g]);
                    }
                }
            }
            __syncthreads();            // buf free for reuse
        }

        // ---- reduce across lanes; keep pair p at lane (p & 31) ----
        float keep0 = 0.f, keep1 = 0.f;
#pragma unroll
        for (int b = 0; b < 8; b++) {
#pragma unroll
            for (int g = 0; g < 8; g++) {
                float2 f2 = *(float2*)&acc[b][g];
                float p = f2.x + f2.y;
#pragma unroll
                for (int off = 16; off > 0; off >>= 1)
                    p += __shfl_xor_sync(0xffffffffu, p, off);
                int pidx = b * 8 + g;
                if (lane == (pidx & 31)) {
                    if (pidx < 32) keep0 = p; else keep1 = p;
                }
            }
        }

        // kHalf 1 publishes partials; kHalf 0 combines, adds U, stores.
        if (kHalf == 1) {
            int g  = lane & 7;
            int b0 = lane >> 3;
            int gl = gGroup * 8 + g;
            red[gl * 16 + (bGroup * 8 + b0)]     = keep0;
            red[gl * 16 + (bGroup * 8 + b0 + 4)] = keep1;
        }
        __syncthreads();
        if (kHalf == 0) {
            int g  = lane & 7;
            int b0 = lane >> 3;
            int gl = gGroup * 8 + g;
#pragma unroll
            for (int h = 0; h < 2; h++) {
                int bb = bGroup * 8 + b0 + h * 4;
                float v = (h ? keep1 : keep0) + red[gl * 16 + bb] + us[bb * 16 + gl];
                size_t o = ((size_t)(bb * T_ + t)) * H_ + gbase + gl;
                out[o] = v;
                if (t == T_ - 1)
                    out[(size_t)B_ * T_ * H_ + (size_t)bb * H_ + gbase + gl] = v;
            }
        }

        __syncthreads();
        if (tid == 0) red_release_add(&g_arrive, 1u);
    }
}

extern "C" void kernel_launch(void* const* d_in, const int* in_sizes, int n_in,
                              void* d_out, int out_size)
{
    const float* x    = (const float*)d_in[0];   // [16, 512, 2048]
    const float* W    = (const float*)d_in[1];   // [2048, 4096]
    const float* bias = (const float*)d_in[2];   // [2048]
    float* out = (float*)d_out;                  // [16*512*2048 + 16*2048]

    float* U = nullptr;
    cudaGetSymbolAddress((void**)&U, g_u);

    cudaFuncSetAttribute(rnn_persistent_kernel,
                         cudaFuncAttributeMaxDynamicSharedMemorySize,
                         SMEM_FLOATS * sizeof(float));

    // reset grid-barrier counter (runs on every graph replay)
    init_kernel<<<1, 1>>>();

    // Phase 1: u = x @ Wx^T + b
    dim3 ggrid(H_ / P1_TN, (B_ * T_) / P1_TM);
    u_gemm_kernel<<<ggrid, 256>>>(x, W, bias, U);

    // Phase 2: persistent recurrence (writes all t and h_last)
    rnn_persistent_kernel<<<NCTA, NTHR, SMEM_FLOATS * sizeof(float)>>>(W, U, out);
}